// round 2
// baseline (speedup 1.0000x reference)
#include <cuda_runtime.h>
#include <math.h>

#define D 32
#define HID 64
#define BATCH 2
#define NQ 512
#define NK 512
#define NROWS (BATCH*NQ + BATCH*NK)   // 2048
#define KD 1152                        // feature dim: 528+528+32+32+2 -> pad 1152

// Scratch (device globals: allocation-free rule)
__device__ float g_H [NROWS * HID];           // 512 KB hidden activations
__device__ float g_L [NROWS * 1024];          // 8 MB   lower-tri factors, row-major 32x32
__device__ float g_FQ[BATCH * NQ * KD];       // 4.5 MB feature rows for Q
__device__ float g_FK[BATCH * NK * KD];       // 4.5 MB feature rows for K

// ---------------------------------------------------------------------------
// Kernel H: h = silu(x @ w1 + b1).  4 rows / block, 256 threads (r = tid>>6).
// ---------------------------------------------------------------------------
__global__ void __launch_bounds__(256) kH(
    const float* __restrict__ Q, const float* __restrict__ K,
    const float* __restrict__ w1, const float* __restrict__ b1)
{
    __shared__ float sx[4 * 32];
    const int tid = threadIdx.x;
    const int rowBase = blockIdx.x * 4;

    if (tid < 128) {
        int r = tid >> 5, c = tid & 31;
        int gr = rowBase + r;
        const float* src = (gr < BATCH * NQ) ? (Q + gr * D)
                                             : (K + (gr - BATCH * NQ) * D);
        sx[tid] = src[c];
    }
    __syncthreads();

    const int r = tid >> 6;        // 0..3
    const int h = tid & 63;        // 0..63
    float acc = b1[h];
    #pragma unroll
    for (int k = 0; k < 32; k++)
        acc = fmaf(sx[r * 32 + k], w1[k * HID + h], acc);
    float s = 1.f / (1.f + expf(-acc));
    g_H[(rowBase + r) * HID + h] = acc * s;
}

// ---------------------------------------------------------------------------
// Kernel R: RAW = H @ w2 + b2, fused L transform (clamp, +I, tril, softplus).
// Tiled GEMM: 64 rows x 64 cols per block, K=64 (single pass), 256 threads,
// 4x4 micro-tile, transposed smem for float4 inner-loop reads.
// ---------------------------------------------------------------------------
__global__ void __launch_bounds__(256) kR(
    const float* __restrict__ w2, const float* __restrict__ b2)
{
    __shared__ float Hs[64 * 68];   // [k][row], pad 68 keeps float4 alignment
    __shared__ float Ws[64 * 64];   // [k][col]

    const int tid = threadIdx.x;
    const int tx = tid & 15;        // col micro group
    const int ty = tid >> 4;        // row micro group
    const int cBase = blockIdx.x * 64;
    const int rowBase = blockIdx.y * 64;

    // Stage H tile (64 rows x 64 k), transposed into Hs[k][row]
    #pragma unroll
    for (int p = 0; p < 4; p++) {
        int idx = tid + p * 256;            // float4 index
        int r = idx >> 4;                   // 0..63
        int k4 = (idx & 15) * 4;            // 0..60
        float4 v = *reinterpret_cast<const float4*>(&g_H[(rowBase + r) * HID + k4]);
        Hs[(k4 + 0) * 68 + r] = v.x;
        Hs[(k4 + 1) * 68 + r] = v.y;
        Hs[(k4 + 2) * 68 + r] = v.z;
        Hs[(k4 + 3) * 68 + r] = v.w;
    }
    // Stage w2 slice (64 k x 64 cols), already [k][col] in global
    #pragma unroll
    for (int p = 0; p < 4; p++) {
        int idx = tid + p * 256;
        int k = idx >> 4;
        int c4 = (idx & 15) * 4;
        float4 v = *reinterpret_cast<const float4*>(&w2[k * 1024 + cBase + c4]);
        *reinterpret_cast<float4*>(&Ws[k * 64 + c4]) = v;
    }
    __syncthreads();

    float acc[4][4] = {};
    #pragma unroll 8
    for (int kk = 0; kk < 64; kk++) {
        float4 a = *reinterpret_cast<const float4*>(&Hs[kk * 68 + ty * 4]);
        float4 b = *reinterpret_cast<const float4*>(&Ws[kk * 64 + tx * 4]);
        acc[0][0] = fmaf(a.x, b.x, acc[0][0]);
        acc[0][1] = fmaf(a.x, b.y, acc[0][1]);
        acc[0][2] = fmaf(a.x, b.z, acc[0][2]);
        acc[0][3] = fmaf(a.x, b.w, acc[0][3]);
        acc[1][0] = fmaf(a.y, b.x, acc[1][0]);
        acc[1][1] = fmaf(a.y, b.y, acc[1][1]);
        acc[1][2] = fmaf(a.y, b.z, acc[1][2]);
        acc[1][3] = fmaf(a.y, b.w, acc[1][3]);
        acc[2][0] = fmaf(a.z, b.x, acc[2][0]);
        acc[2][1] = fmaf(a.z, b.y, acc[2][1]);
        acc[2][2] = fmaf(a.z, b.z, acc[2][2]);
        acc[2][3] = fmaf(a.z, b.w, acc[2][3]);
        acc[3][0] = fmaf(a.w, b.x, acc[3][0]);
        acc[3][1] = fmaf(a.w, b.y, acc[3][1]);
        acc[3][2] = fmaf(a.w, b.z, acc[3][2]);
        acc[3][3] = fmaf(a.w, b.w, acc[3][3]);
    }

    // Epilogue: raw -> L element, write g_L
    #pragma unroll
    for (int rr = 0; rr < 4; rr++) {
        int gr = rowBase + ty * 4 + rr;
        #pragma unroll
        for (int cc = 0; cc < 4; cc++) {
            int e = cBase + tx * 4 + cc;
            int i = e >> 5, j = e & 31;
            float raw = acc[rr][cc] + b2[e];
            float t = 5.f * tanhf(raw * 0.2f);
            float Lv;
            if (j > i) {
                Lv = 0.f;
            } else if (j == i) {
                float z = t + 1.f;
                Lv = fmaxf(z, 0.f) + log1pf(expf(-fabsf(z))) + 1e-4f;
            } else {
                Lv = t;
            }
            g_L[gr * 1024 + e] = Lv;
        }
    }
}

// ---------------------------------------------------------------------------
// Kernel B: per-row G = L L^T, u = G x, a = x^T G x, emit feature row.
// One row per block, 256 threads. (i,j)-driven indexing — no sqrt search.
// Feature layout (KD=1152):
//   FQ: [0..527]=packGq(dbl offdiag) [528..1055]=qq-pack [1056..]=u [1088..]=q
//       [1120]=a [1121]=1 [1122..]=0
//   FK: [0..527]=kk-pack [528..1055]=packGk(dbl) [1056..]=-2k [1088..]=-2u
//       [1120]=1 [1121]=a [1122..]=0
// ---------------------------------------------------------------------------
__global__ void __launch_bounds__(256) kB(
    const float* __restrict__ Q, const float* __restrict__ K)
{
    __shared__ float sL[1024];
    __shared__ float sG[1024];
    __shared__ float sx[32];

    const int tid = threadIdx.x;
    const int gr = blockIdx.x;
    const bool qrow = (gr < BATCH * NQ);
    const float* src = qrow ? (Q + gr * D) : (K + (gr - BATCH * NQ) * D);

    {   // coalesced float4 load of L row (1024 floats)
        float4 v = *reinterpret_cast<const float4*>(&g_L[gr * 1024 + tid * 4]);
        *reinterpret_cast<float4*>(&sL[tid * 4]) = v;
    }
    if (tid < 32) sx[tid] = src[tid];
    __syncthreads();

    // Full G matrix (symmetric): G[i][j] = sum_{t<=min(i,j)} L[i][t]L[j][t]
    #pragma unroll
    for (int t = tid; t < 1024; t += 256) {
        int i = t >> 5, j = t & 31;
        int mn = (i < j) ? i : j;
        float s = 0.f;
        for (int tt = 0; tt <= mn; tt++)
            s = fmaf(sL[i * 32 + tt], sL[j * 32 + tt], s);
        sG[t] = s;
    }
    __syncthreads();

    float* F = qrow ? (g_FQ + gr * KD)
                    : (g_FK + (gr - BATCH * NQ) * KD);

    // warp 0: u = G x, a = u . x, vector/scalar features
    if (tid < 32) {
        float u = 0.f;
        #pragma unroll
        for (int j = 0; j < 32; j++)
            u = fmaf(sG[tid * 32 + j], sx[j], u);
        float prod = u * sx[tid];
        #pragma unroll
        for (int off = 16; off > 0; off >>= 1)
            prod += __shfl_xor_sync(0xffffffffu, prod, off);
        // prod == a on all lanes now
        F[1056 + tid] = qrow ? u        : -2.f * sx[tid];
        F[1088 + tid] = qrow ? sx[tid]  : -2.f * u;
        if (tid == 0) {
            F[1120] = qrow ? prod : 1.f;
            F[1121] = qrow ? 1.f  : prod;
        }
    }
    if (tid < 30) F[1122 + tid] = 0.f;

    // packed quadratic features
    #pragma unroll
    for (int t = tid; t < 1024; t += 256) {
        int i = t >> 5, j = t & 31;
        if (j <= i) {
            int e = ((i * (i + 1)) >> 1) + j;
            float g = sG[t];
            float packG = (i == j) ? g : 2.f * g;
            float xx = sx[i] * sx[j];
            F[e]       = qrow ? packG : xx;
            F[528 + e] = qrow ? xx : packG;
        }
    }
}

// ---------------------------------------------------------------------------
// Kernel C: per batch  C[n][m] = sqrt(clip(0.5 * FQ[n] . FK[m]))
// NT-GEMM, 64x64 tile, 256 threads, 4x4 micro-tile, K chunk 32,
// transposed smem [k][n] so the inner loop is 2 x LDS.128 + 16 FMA.
// ---------------------------------------------------------------------------
__global__ void __launch_bounds__(256) kC(float* __restrict__ out)
{
    __shared__ float As[32 * 68];
    __shared__ float Bs[32 * 68];

    const int tid = threadIdx.x;
    const int tx = tid & 15;         // m micro
    const int ty = tid >> 4;         // n micro
    const int b = blockIdx.z;
    const int nBase = blockIdx.y * 64;
    const int mBase = blockIdx.x * 64;

    const float* Ag = g_FQ + (size_t)(b * NQ + nBase) * KD;
    const float* Bg = g_FK + (size_t)(b * NK + mBase) * KD;

    float acc[4][4] = {};

    const int lr = tid >> 3;          // 0..31
    const int kq = (tid & 7) * 4;     // 0..28

    for (int k0 = 0; k0 < KD; k0 += 32) {
        __syncthreads();
        #pragma unroll
        for (int half = 0; half < 2; half++) {
            int r = lr + half * 32;
            float4 va = *reinterpret_cast<const float4*>(&Ag[(size_t)r * KD + k0 + kq]);
            float4 vb = *reinterpret_cast<const float4*>(&Bg[(size_t)r * KD + k0 + kq]);
            As[(kq + 0) * 68 + r] = va.x;
            As[(kq + 1) * 68 + r] = va.y;
            As[(kq + 2) * 68 + r] = va.z;
            As[(kq + 3) * 68 + r] = va.w;
            Bs[(kq + 0) * 68 + r] = vb.x;
            Bs[(kq + 1) * 68 + r] = vb.y;
            Bs[(kq + 2) * 68 + r] = vb.z;
            Bs[(kq + 3) * 68 + r] = vb.w;
        }
        __syncthreads();

        #pragma unroll
        for (int kk = 0; kk < 32; kk++) {
            float4 a = *reinterpret_cast<const float4*>(&As[kk * 68 + ty * 4]);
            float4 bv = *reinterpret_cast<const float4*>(&Bs[kk * 68 + tx * 4]);
            acc[0][0] = fmaf(a.x, bv.x, acc[0][0]);
            acc[0][1] = fmaf(a.x, bv.y, acc[0][1]);
            acc[0][2] = fmaf(a.x, bv.z, acc[0][2]);
            acc[0][3] = fmaf(a.x, bv.w, acc[0][3]);
            acc[1][0] = fmaf(a.y, bv.x, acc[1][0]);
            acc[1][1] = fmaf(a.y, bv.y, acc[1][1]);
            acc[1][2] = fmaf(a.y, bv.z, acc[1][2]);
            acc[1][3] = fmaf(a.y, bv.w, acc[1][3]);
            acc[2][0] = fmaf(a.z, bv.x, acc[2][0]);
            acc[2][1] = fmaf(a.z, bv.y, acc[2][1]);
            acc[2][2] = fmaf(a.z, bv.z, acc[2][2]);
            acc[2][3] = fmaf(a.z, bv.w, acc[2][3]);
            acc[3][0] = fmaf(a.w, bv.x, acc[3][0]);
            acc[3][1] = fmaf(a.w, bv.y, acc[3][1]);
            acc[3][2] = fmaf(a.w, bv.z, acc[3][2]);
            acc[3][3] = fmaf(a.w, bv.w, acc[3][3]);
        }
    }

    #pragma unroll
    for (int i = 0; i < 4; i++) {
        int n = nBase + ty * 4 + i;
        #pragma unroll
        for (int j = 0; j < 4; j++) {
            int m = mBase + tx * 4 + j;
            float d = 0.5f * acc[i][j];
            d = fminf(fmaxf(d, 1e-6f), 1e6f);
            out[((size_t)b * NQ + n) * NK + m] = sqrtf(d);
        }
    }
}

// ---------------------------------------------------------------------------
extern "C" void kernel_launch(void* const* d_in, const int* in_sizes, int n_in,
                              void* d_out, int out_size)
{
    const float* Q  = (const float*)d_in[0];
    const float* K  = (const float*)d_in[1];
    const float* w1 = (const float*)d_in[2];
    const float* b1 = (const float*)d_in[3];
    const float* w2 = (const float*)d_in[4];
    const float* b2 = (const float*)d_in[5];
    float* out = (float*)d_out;

    kH<<<NROWS / 4, 256>>>(Q, K, w1, b1);
    dim3 gr(1024 / 64, NROWS / 64);
    kR<<<gr, 256>>>(w2, b2);
    kB<<<NROWS, 256>>>(Q, K);
    dim3 gc(NK / 64, NQ / 64, BATCH);
    kC<<<gc, 256>>>(out);
}

// round 5
// speedup vs baseline: 1.4328x; 1.4328x over previous
#include <cuda_runtime.h>
#include <cuda_bf16.h>
#include <math.h>
#include <stdint.h>

#define D 32
#define HID 64
#define BATCH 2
#define NQ 512
#define NK 512
#define NROWS (BATCH*NQ + BATCH*NK)   // 2048
#define KD 1152                        // logical feature dim
#define KEXT 3456                      // bf16 extended: A=[hi|lo|hi], B=[hi|hi|lo]
#define CHUNK 64                       // bf16 per K-chunk (128 B rows)
#define NCHUNK (KEXT/CHUNK)            // 54
#define STAGES 3

// Scratch (device globals: allocation-free rule)
__device__ float g_H [NROWS * HID];                        // 0.5 MB
__device__ float g_L [NROWS * 1024];                       // 8 MB
__device__ __nv_bfloat16 g_Ae[(size_t)BATCH * NQ * KEXT];  // 7 MB
__device__ __nv_bfloat16 g_Be[(size_t)BATCH * NK * KEXT];  // 7 MB

__device__ __forceinline__ uint32_t smem_u32(const void* p) {
    uint32_t a;
    asm("{ .reg .u64 t; cvta.to.shared.u64 t, %1; cvt.u32.u64 %0, t; }"
        : "=r"(a) : "l"(p));
    return a;
}

// ---------------------------------------------------------------------------
// Kernel H: h = silu(x @ w1 + b1).  4 rows / block, 256 threads.
// ---------------------------------------------------------------------------
__global__ void __launch_bounds__(256) kH(
    const float* __restrict__ Q, const float* __restrict__ K,
    const float* __restrict__ w1, const float* __restrict__ b1)
{
    __shared__ float sx[4 * 32];
    const int tid = threadIdx.x;
    const int rowBase = blockIdx.x * 4;

    if (tid < 128) {
        int r = tid >> 5, c = tid & 31;
        int gr = rowBase + r;
        const float* src = (gr < BATCH * NQ) ? (Q + gr * D)
                                             : (K + (gr - BATCH * NQ) * D);
        sx[tid] = src[c];
    }
    __syncthreads();

    const int r = tid >> 6;
    const int h = tid & 63;
    float acc = b1[h];
    #pragma unroll
    for (int k = 0; k < 32; k++)
        acc = fmaf(sx[r * 32 + k], w1[k * HID + h], acc);
    float s = 1.f / (1.f + expf(-acc));
    g_H[(rowBase + r) * HID + h] = acc * s;
}

// ---------------------------------------------------------------------------
// Kernel R: RAW = H @ w2 + b2, fused L transform (clamp, +I, tril, softplus).
// 64x64 tile, 256 threads, 4x4 micro-tile, natural [row][k] Hs staging.
// ---------------------------------------------------------------------------
__global__ void __launch_bounds__(256) kR(
    const float* __restrict__ w2, const float* __restrict__ b2)
{
    __shared__ float Hs[64 * 68];   // [row][k]
    __shared__ float Ws[64 * 64];   // [k][col]

    const int tid = threadIdx.x;
    const int tx = tid & 15;
    const int ty = tid >> 4;
    const int cBase = blockIdx.x * 64;
    const int rowBase = blockIdx.y * 64;

    #pragma unroll
    for (int p = 0; p < 4; p++) {
        int idx = tid + p * 256;
        int r = idx >> 4;
        int k4 = (idx & 15) * 4;
        float4 v = *reinterpret_cast<const float4*>(&g_H[(rowBase + r) * HID + k4]);
        *reinterpret_cast<float4*>(&Hs[r * 68 + k4]) = v;
    }
    #pragma unroll
    for (int p = 0; p < 4; p++) {
        int idx = tid + p * 256;
        int k = idx >> 4;
        int c4 = (idx & 15) * 4;
        float4 v = *reinterpret_cast<const float4*>(&w2[k * 1024 + cBase + c4]);
        *reinterpret_cast<float4*>(&Ws[k * 64 + c4]) = v;
    }
    __syncthreads();

    float acc[4][4] = {};
    #pragma unroll 8
    for (int kk = 0; kk < 64; kk++) {
        float a0 = Hs[(ty * 4 + 0) * 68 + kk];
        float a1 = Hs[(ty * 4 + 1) * 68 + kk];
        float a2 = Hs[(ty * 4 + 2) * 68 + kk];
        float a3 = Hs[(ty * 4 + 3) * 68 + kk];
        float4 b = *reinterpret_cast<const float4*>(&Ws[kk * 64 + tx * 4]);
        acc[0][0] = fmaf(a0, b.x, acc[0][0]);
        acc[0][1] = fmaf(a0, b.y, acc[0][1]);
        acc[0][2] = fmaf(a0, b.z, acc[0][2]);
        acc[0][3] = fmaf(a0, b.w, acc[0][3]);
        acc[1][0] = fmaf(a1, b.x, acc[1][0]);
        acc[1][1] = fmaf(a1, b.y, acc[1][1]);
        acc[1][2] = fmaf(a1, b.z, acc[1][2]);
        acc[1][3] = fmaf(a1, b.w, acc[1][3]);
        acc[2][0] = fmaf(a2, b.x, acc[2][0]);
        acc[2][1] = fmaf(a2, b.y, acc[2][1]);
        acc[2][2] = fmaf(a2, b.z, acc[2][2]);
        acc[2][3] = fmaf(a2, b.w, acc[2][3]);
        acc[3][0] = fmaf(a3, b.x, acc[3][0]);
        acc[3][1] = fmaf(a3, b.y, acc[3][1]);
        acc[3][2] = fmaf(a3, b.z, acc[3][2]);
        acc[3][3] = fmaf(a3, b.w, acc[3][3]);
    }

    #pragma unroll
    for (int rr = 0; rr < 4; rr++) {
        int gr = rowBase + ty * 4 + rr;
        #pragma unroll
        for (int cc = 0; cc < 4; cc++) {
            int e = cBase + tx * 4 + cc;
            int i = e >> 5, j = e & 31;
            float raw = acc[rr][cc] + b2[e];
            float t = 5.f * tanhf(raw * 0.2f);
            float Lv;
            if (j > i) {
                Lv = 0.f;
            } else if (j == i) {
                float z = t + 1.f;
                Lv = fmaxf(z, 0.f) + log1pf(expf(-fabsf(z))) + 1e-4f;
            } else {
                Lv = t;
            }
            g_L[gr * 1024 + e] = Lv;
        }
    }
}

// ---------------------------------------------------------------------------
// Kernel B2: per-row G = L L^T, u = G x, a = x^T G x; write bf16 hi/lo
// K-extended feature rows directly (fused old kB + kX).
// Segment layout within a KEXT row: A rows [hi | lo | hi], B rows [hi | hi | lo].
// Logical feature layout (per 1152 segment):
//   A(Q): [0..527]=packGq(dbl offdiag) [528..1055]=qq-pack [1056..]=u [1088..]=q
//         [1120]=a [1121]=1 [1122..]=0
//   B(K): [0..527]=kk-pack [528..1055]=packGk(dbl) [1056..]=-2k [1088..]=-2u
//         [1120]=1 [1121]=a [1122..]=0
// ---------------------------------------------------------------------------
__device__ __forceinline__ void store3(__nv_bfloat16* __restrict__ E, int e,
                                       float v, bool isA)
{
    __nv_bfloat16 h = __float2bfloat16(v);
    __nv_bfloat16 l = __float2bfloat16(v - __bfloat162float(h));
    E[e] = h;
    E[1152 + e] = isA ? l : h;
    E[2304 + e] = isA ? h : l;
}

__global__ void __launch_bounds__(256) kB2(
    const float* __restrict__ Q, const float* __restrict__ K)
{
    __shared__ float sL[1024];
    __shared__ float sG[1024];
    __shared__ float sx[32];

    const int tid = threadIdx.x;
    const int gr = blockIdx.x;
    const bool isA = (gr < BATCH * NQ);
    const float* src = isA ? (Q + gr * D) : (K + (gr - BATCH * NQ) * D);

    {
        float4 v = *reinterpret_cast<const float4*>(&g_L[gr * 1024 + tid * 4]);
        *reinterpret_cast<float4*>(&sL[tid * 4]) = v;
    }
    if (tid < 32) sx[tid] = src[tid];
    __syncthreads();

    #pragma unroll
    for (int t = tid; t < 1024; t += 256) {
        int i = t >> 5, j = t & 31;
        int mn = (i < j) ? i : j;
        float s = 0.f;
        for (int tt = 0; tt <= mn; tt++)
            s = fmaf(sL[i * 32 + tt], sL[j * 32 + tt], s);
        sG[t] = s;
    }
    __syncthreads();

    __nv_bfloat16* E = isA ? (g_Ae + (size_t)gr * KEXT)
                           : (g_Be + (size_t)(gr - BATCH * NQ) * KEXT);

    if (tid < 32) {
        float u = 0.f;
        #pragma unroll
        for (int j = 0; j < 32; j++)
            u = fmaf(sG[tid * 32 + j], sx[j], u);
        float prod = u * sx[tid];
        #pragma unroll
        for (int off = 16; off > 0; off >>= 1)
            prod += __shfl_xor_sync(0xffffffffu, prod, off);
        store3(E, 1056 + tid, isA ? u : -2.f * sx[tid], isA);
        store3(E, 1088 + tid, isA ? sx[tid] : -2.f * u, isA);
        if (tid == 0) {
            store3(E, 1120, isA ? prod : 1.f, isA);
            store3(E, 1121, isA ? 1.f : prod, isA);
        }
    }
    if (tid < 30) store3(E, 1122 + tid, 0.f, isA);

    #pragma unroll
    for (int t = tid; t < 1024; t += 256) {
        int i = t >> 5, j = t & 31;
        if (j <= i) {
            int e = ((i * (i + 1)) >> 1) + j;
            float g = sG[t];
            float packG = (i == j) ? g : 2.f * g;
            float xx = sx[i] * sx[j];
            store3(E, e,       isA ? packG : xx, isA);
            store3(E, 528 + e, isA ? xx : packG, isA);
        }
    }
}

// ---------------------------------------------------------------------------
// Kernel Cm: bf16 mma.sync GEMM.  out[b,n,m] = sqrt(clip(0.5 * Ae[n].Be[m]))
// CTA: 64(M) x 64(N), 128 threads = 2x2 warps, warp tile 32x32.
// K in 54 chunks of 64; 3-stage cp.async pipeline; xor-swizzled smem.
// ---------------------------------------------------------------------------
__global__ void __launch_bounds__(128) kCm(float* __restrict__ out)
{
    __shared__ __align__(1024) uint8_t sbuf[STAGES * 16384];   // 48 KB

    const int tid  = threadIdx.x;
    const int wid  = tid >> 5;
    const int lane = tid & 31;
    const int wm = wid & 1;          // M warp coord (2)
    const int wn = wid >> 1;         // N warp coord (2)
    const int b  = blockIdx.z;
    const int aRow0 = b * NQ + blockIdx.y * 64;
    const int bRow0 = b * NK + blockIdx.x * 64;

    const uint32_t sb = smem_u32(sbuf);

    // per-thread cp.async source/dest precompute: 8 x 16B per chunk
    const __nv_bfloat16* srcP[8];
    uint32_t dstOff[8];
    #pragma unroll
    for (int p = 0; p < 8; p++) {
        int idx = tid + p * 128;          // 0..1023
        int isB = idx >> 9;
        int li  = idx & 511;
        int row = li >> 3;                // 0..63
        int q   = li & 7;                 // 16B unit
        srcP[p] = (isB ? (g_Be + (size_t)(bRow0 + row) * KEXT)
                       : (g_Ae + (size_t)(aRow0 + row) * KEXT)) + q * 8;
        dstOff[p] = (uint32_t)(isB * 8192 + row * 128 + ((q ^ (row & 7)) << 4));
    }

    #define ISSUE(c, s)                                                        \
        do {                                                                   \
            uint32_t base_ = sb + (s) * 16384;                                 \
            _Pragma("unroll")                                                  \
            for (int p_ = 0; p_ < 8; p_++) {                                   \
                uint32_t d_ = base_ + dstOff[p_];                              \
                const void* g_ = (const void*)(srcP[p_] + (c) * CHUNK);        \
                asm volatile("cp.async.cg.shared.global [%0], [%1], 16;"       \
                             :: "r"(d_), "l"(g_) : "memory");                  \
            }                                                                  \
        } while (0)

    // prologue: fill 3 stages
    ISSUE(0, 0); asm volatile("cp.async.commit_group;" ::: "memory");
    ISSUE(1, 1); asm volatile("cp.async.commit_group;" ::: "memory");
    ISSUE(2, 2); asm volatile("cp.async.commit_group;" ::: "memory");

    float acc[2][4][4] = {};   // [mt][j][c0..c3]

    for (int c = 0; c < NCHUNK; c++) {
        asm volatile("cp.async.wait_group 2;" ::: "memory");
        __syncthreads();

        const int s = c % STAGES;
        const uint32_t Ab = sb + s * 16384;
        const uint32_t Bb = Ab + 8192;

        #pragma unroll
        for (int ks = 0; ks < 4; ks++) {
            uint32_t a[2][4], bb[2][4];
            const int tile = lane >> 3;
            const int rin  = lane & 7;
            const int rofs = ((tile & 1) << 3) + rin;
            const int ku   = 2 * ks + (tile >> 1);
            #pragma unroll
            for (int mt = 0; mt < 2; mt++) {
                int r = wm * 32 + mt * 16 + rofs;
                uint32_t ad = Ab + r * 128 + ((ku ^ (r & 7)) << 4);
                asm volatile(
                    "ldmatrix.sync.aligned.m8n8.x4.shared.b16 {%0,%1,%2,%3}, [%4];"
                    : "=r"(a[mt][0]), "=r"(a[mt][1]), "=r"(a[mt][2]), "=r"(a[mt][3])
                    : "r"(ad));
            }
            #pragma unroll
            for (int nt = 0; nt < 2; nt++) {
                int r = wn * 32 + nt * 16 + rofs;
                uint32_t bd = Bb + r * 128 + ((ku ^ (r & 7)) << 4);
                asm volatile(
                    "ldmatrix.sync.aligned.m8n8.x4.shared.b16 {%0,%1,%2,%3}, [%4];"
                    : "=r"(bb[nt][0]), "=r"(bb[nt][1]), "=r"(bb[nt][2]), "=r"(bb[nt][3])
                    : "r"(bd));
            }
            #pragma unroll
            for (int mt = 0; mt < 2; mt++) {
                #pragma unroll
                for (int j = 0; j < 4; j++) {
                    uint32_t b0 = bb[j >> 1][(j & 1)];
                    uint32_t b1 = bb[j >> 1][(j & 1) + 2];
                    asm volatile(
                        "mma.sync.aligned.m16n8k16.row.col.f32.bf16.bf16.f32 "
                        "{%0,%1,%2,%3}, {%4,%5,%6,%7}, {%8,%9}, {%0,%1,%2,%3};"
                        : "+f"(acc[mt][j][0]), "+f"(acc[mt][j][1]),
                          "+f"(acc[mt][j][2]), "+f"(acc[mt][j][3])
                        : "r"(a[mt][0]), "r"(a[mt][1]), "r"(a[mt][2]), "r"(a[mt][3]),
                          "r"(b0), "r"(b1));
                }
            }
        }

        __syncthreads();
        if (c + STAGES < NCHUNK) ISSUE(c + STAGES, s);
        asm volatile("cp.async.commit_group;" ::: "memory");
    }

    // epilogue: sqrt(clip(0.5*acc)) -> out
    const int g = lane >> 2;
    const int t2 = (lane & 3) * 2;
    #pragma unroll
    for (int mt = 0; mt < 2; mt++) {
        int n = blockIdx.y * 64 + wm * 32 + mt * 16 + g;
        #pragma unroll
        for (int j = 0; j < 4; j++) {
            int m = blockIdx.x * 64 + wn * 32 + j * 8 + t2;
            float d0 = 0.5f * acc[mt][j][0];
            float d1 = 0.5f * acc[mt][j][1];
            float d2 = 0.5f * acc[mt][j][2];
            float d3 = 0.5f * acc[mt][j][3];
            d0 = fminf(fmaxf(d0, 1e-6f), 1e6f);
            d1 = fminf(fmaxf(d1, 1e-6f), 1e6f);
            d2 = fminf(fmaxf(d2, 1e-6f), 1e6f);
            d3 = fminf(fmaxf(d3, 1e-6f), 1e6f);
            float2 lo = make_float2(sqrtf(d0), sqrtf(d1));
            float2 hi = make_float2(sqrtf(d2), sqrtf(d3));
            *reinterpret_cast<float2*>(&out[((size_t)(b * NQ + n) * NK) + m]) = lo;
            *reinterpret_cast<float2*>(&out[((size_t)(b * NQ + n + 8) * NK) + m]) = hi;
        }
    }
    #undef ISSUE
}

// ---------------------------------------------------------------------------
extern "C" void kernel_launch(void* const* d_in, const int* in_sizes, int n_in,
                              void* d_out, int out_size)
{
    const float* Q  = (const float*)d_in[0];
    const float* K  = (const float*)d_in[1];
    const float* w1 = (const float*)d_in[2];
    const float* b1 = (const float*)d_in[3];
    const float* w2 = (const float*)d_in[4];
    const float* b2 = (const float*)d_in[5];
    float* out = (float*)d_out;

    kH<<<NROWS / 4, 256>>>(Q, K, w1, b1);
    dim3 gr(1024 / 64, NROWS / 64);
    kR<<<gr, 256>>>(w2, b2);
    kB2<<<NROWS, 256>>>(Q, K);
    dim3 gc(NK / 64, NQ / 64, BATCH);
    kCm<<<gc, 128>>>(out);
}